// round 5
// baseline (speedup 1.0000x reference)
#include <cuda_runtime.h>
#include <cuda_bf16.h>
#include <cstdint>

// Problem dims
#define B_   256
#define T_   32
#define IN_  2312
#define H_   1024
#define OUT_ 10
#define BH   (B_ * H_)
#define KP   2432              // IN_ padded to multiple of 32
#define KSPL 8                 // split-K for GEMM2

// LIF constants
#define DT_TAUMEM 0.05f
#define DT_TAUSYN 0.2f

typedef __nv_bfloat16 bf16;

// ------------------------- device globals (scratch) -------------------------
__device__ float g_inp1[(long)T_ * BH];
__device__ float g_v1[BH], g_i1[BH];
__device__ float g_v2[BH], g_i2[BH];
__device__ float g_part[(long)KSPL * BH];
__device__ float g_vo[B_ * OUT_], g_io[B_ * OUT_];

// bf16 limb planes (3-limb exact fp32 decomposition)
__device__ bf16 g_x0[(long)(B_*T_) * KP], g_x1[(long)(B_*T_) * KP], g_x2[(long)(B_*T_) * KP];
__device__ bf16 g_w10[(long)H_ * KP],     g_w11[(long)H_ * KP],     g_w12[(long)H_ * KP];
__device__ bf16 g_w20[(long)H_ * H_],     g_w21[(long)H_ * H_],     g_w22[(long)H_ * H_];
__device__ bf16 g_s1h[BH];               // layer-1 spikes (exact in bf16)

// ------------------------------ LIF ----------------------------------------
__device__ __forceinline__ void lif_update(float& v, float& cur, float inp, float& s) {
    float vd = v + DT_TAUMEM * (cur - v);
    float id = cur - DT_TAUSYN * cur;
    s = (vd - 1.0f) > 0.0f ? 1.0f : 0.0f;
    v = (1.0f - s) * vd;
    cur = id + inp;
}

// --------------------------- PTX helpers ------------------------------------
__device__ __forceinline__ uint32_t smem_u32(const void* p) {
    uint32_t a;
    asm("{ .reg .u64 t; cvta.to.shared.u64 t, %1; cvt.u32.u64 %0, t; }" : "=r"(a) : "l"(p));
    return a;
}
__device__ __forceinline__ void ldsm4(uint32_t* r, uint32_t a) {
    asm volatile("ldmatrix.sync.aligned.m8n8.x4.shared.b16 {%0,%1,%2,%3}, [%4];"
                 : "=r"(r[0]), "=r"(r[1]), "=r"(r[2]), "=r"(r[3]) : "r"(a));
}
__device__ __forceinline__ void mmabf(float* c, const uint32_t* a, const uint32_t* b) {
    asm volatile(
        "mma.sync.aligned.m16n8k16.row.col.f32.bf16.bf16.f32 "
        "{%0,%1,%2,%3}, {%4,%5,%6,%7}, {%8,%9}, {%0,%1,%2,%3};"
        : "+f"(c[0]), "+f"(c[1]), "+f"(c[2]), "+f"(c[3])
        : "r"(a[0]), "r"(a[1]), "r"(a[2]), "r"(a[3]), "r"(b[0]), "r"(b[1]));
}
// load a 128x32 bf16 tile into smem with row pitch 40 (conflict-benign for ldmatrix)
__device__ __forceinline__ void ldtile(bf16* sm, const bf16* g, long gstride) {
    for (int i = threadIdx.x; i < 512; i += 256) {
        int r = i >> 2, c = (i & 3) * 8;
        *(uint4*)(sm + r * 40 + c) = *(const uint4*)(g + (long)r * gstride + c);
    }
}

// --------------------------- init ------------------------------------------
__global__ void init_kernel(float* __restrict__ out) {
    int idx = blockIdx.x * blockDim.x + threadIdx.x;
    if (idx < BH) {
        g_v1[idx] = 0.f; g_i1[idx] = 0.f;
        g_v2[idx] = 0.f; g_i2[idx] = 0.f;
    }
    if (idx < B_ * OUT_) {
        g_vo[idx] = 0.f; g_io[idx] = 0.f;
        out[idx] = 0.f;
    }
}

// -------------------- fp32 -> 3 bf16 limbs (exact), with K padding ----------
__global__ void conv3(const float* __restrict__ src,
                      bf16* __restrict__ d0, bf16* __restrict__ d1, bf16* __restrict__ d2,
                      int ksrc, int kdst) {
    int row = blockIdx.y;
    int k = blockIdx.x * 256 + threadIdx.x;
    if (k >= kdst) return;
    float v = (k < ksrc) ? src[(long)row * ksrc + k] : 0.f;
    bf16 h0 = __float2bfloat16(v);
    float r1 = v - __bfloat162float(h0);
    bf16 h1 = __float2bfloat16(r1);
    bf16 h2 = __float2bfloat16(r1 - __bfloat162float(h1));
    long o = (long)row * kdst + k;
    d0[o] = h0; d1[o] = h1; d2[o] = h2;
}

// ---------------------------------------------------------------------------
// GEMM1 (mma.sync bf16, 6 limb pairs): C[m][h] = x[m,:].W1[h,:] (+b1)
// M=8192, N=1024, K=KP. Block 128x128, BK=32, 8 warps (warp tile 32x64).
// dyn smem: 6 planes x 128x40 bf16 = 61440 B.
// ---------------------------------------------------------------------------
__global__ void __launch_bounds__(256) mm1_kernel(const float* __restrict__ b1)
{
    extern __shared__ bf16 sm[];
    bf16* smA[3] = { sm, sm + 5120, sm + 10240 };          // x planes
    bf16* smB[3] = { sm + 15360, sm + 20480, sm + 25600 }; // W1 planes

    int tid = threadIdx.x, wid = tid >> 5, lane = tid & 31;
    int m0 = blockIdx.y * 128;
    int n0 = blockIdx.x * 128;
    int wm = (wid & 3) * 32, wn = (wid >> 2) * 64;

    uint32_t sa[3], sb[3];
#pragma unroll
    for (int p = 0; p < 3; p++) { sa[p] = smem_u32(smA[p]); sb[p] = smem_u32(smB[p]); }

    float C[2][8][4];
#pragma unroll
    for (int f = 0; f < 2; f++)
#pragma unroll
        for (int j = 0; j < 8; j++)
#pragma unroll
            for (int e = 0; e < 4; e++) C[f][j][e] = 0.f;

    const bf16* xg[3] = { g_x0, g_x1, g_x2 };
    const bf16* wg[3] = { g_w10, g_w11, g_w12 };
    const int pa[6] = {0, 0, 1, 0, 2, 1};
    const int pb[6] = {0, 1, 0, 2, 0, 1};

    // per-lane ldmatrix address offsets (in elements)
    int arow = (lane & 15), acol8 = (lane >> 4) << 3;
    int brow = ((lane >> 4) << 3) + (lane & 7), bcol8 = ((lane >> 3) & 1) << 3;

    for (int kt = 0; kt < KP / 32; kt++) {
        long ko = (long)kt * 32;
#pragma unroll
        for (int p = 0; p < 3; p++) {
            ldtile(smA[p], xg[p] + (long)m0 * KP + ko, KP);
            ldtile(smB[p], wg[p] + (long)n0 * KP + ko, KP);
        }
        __syncthreads();
#pragma unroll
        for (int kk = 0; kk < 32; kk += 16) {
            uint32_t Af[3][2][4];
#pragma unroll
            for (int p = 0; p < 3; p++)
#pragma unroll
                for (int f = 0; f < 2; f++)
                    ldsm4(Af[p][f], sa[p] + ((wm + f * 16 + arow) * 40 + kk + acol8) * 2);
#pragma unroll
            for (int nc = 0; nc < 4; nc++) {
                uint32_t Bf[3][4];
#pragma unroll
                for (int p = 0; p < 3; p++)
                    ldsm4(Bf[p], sb[p] + ((wn + nc * 16 + brow) * 40 + kk + bcol8) * 2);
#pragma unroll
                for (int q = 0; q < 6; q++)
#pragma unroll
                    for (int f = 0; f < 2; f++)
#pragma unroll
                        for (int j = 0; j < 2; j++)
                            mmabf(C[f][nc * 2 + j], Af[pa[q]][f], &Bf[pb[q]][j * 2]);
            }
        }
        __syncthreads();
    }

    // epilogue: add bias, scatter C[m][h] to g_inp1[t][b][h]
#pragma unroll
    for (int f = 0; f < 2; f++) {
        int rl = m0 + wm + f * 16 + (lane >> 2);
#pragma unroll
        for (int j = 0; j < 8; j++) {
            int h = n0 + wn + j * 8 + (lane & 3) * 2;
            float bx = b1[h], by = b1[h + 1];
            int m = rl;
            {
                int b = m >> 5, t = m & 31;
                *(float2*)&g_inp1[((long)t * B_ + b) * H_ + h] =
                    make_float2(C[f][j][0] + bx, C[f][j][1] + by);
            }
            m = rl + 8;
            {
                int b = m >> 5, t = m & 31;
                *(float2*)&g_inp1[((long)t * B_ + b) * H_ + h] =
                    make_float2(C[f][j][2] + bx, C[f][j][3] + by);
            }
        }
    }
}

// ---------------------------------------------------------------------------
// GEMM2 (mma.sync bf16, 3 limb pairs) split-K partial:
// g_part[z][b][h] = sum_{k in chunk z} s1[b,k] * W2[h,k]
// Block 128(m=batch) x 128(n=h), K chunk 128 (4 k-tiles). Grid (8, 2, KSPL).
// ---------------------------------------------------------------------------
__global__ void __launch_bounds__(256) g2_kernel()
{
    __shared__ bf16 smA[128 * 40];
    __shared__ bf16 smB[3][128 * 40];

    int tid = threadIdx.x, wid = tid >> 5, lane = tid & 31;
    int n0 = blockIdx.x * 128;
    int m0 = blockIdx.y * 128;
    int kbase = blockIdx.z * (H_ / KSPL);
    int wm = (wid & 3) * 32, wn = (wid >> 2) * 64;

    uint32_t sa = smem_u32(smA);
    uint32_t sb[3] = { smem_u32(smB[0]), smem_u32(smB[1]), smem_u32(smB[2]) };

    float C[2][8][4];
#pragma unroll
    for (int f = 0; f < 2; f++)
#pragma unroll
        for (int j = 0; j < 8; j++)
#pragma unroll
            for (int e = 0; e < 4; e++) C[f][j][e] = 0.f;

    const bf16* wg[3] = { g_w20, g_w21, g_w22 };

    int arow = (lane & 15), acol8 = (lane >> 4) << 3;
    int brow = ((lane >> 4) << 3) + (lane & 7), bcol8 = ((lane >> 3) & 1) << 3;

#pragma unroll
    for (int kt = 0; kt < 4; kt++) {
        long ko = kbase + kt * 32;
        ldtile(smA, g_s1h + (long)m0 * H_ + ko, H_);
#pragma unroll
        for (int p = 0; p < 3; p++)
            ldtile(smB[p], wg[p] + (long)n0 * H_ + ko, H_);
        __syncthreads();
#pragma unroll
        for (int kk = 0; kk < 32; kk += 16) {
            uint32_t Af[2][4];
#pragma unroll
            for (int f = 0; f < 2; f++)
                ldsm4(Af[f], sa + ((wm + f * 16 + arow) * 40 + kk + acol8) * 2);
#pragma unroll
            for (int nc = 0; nc < 4; nc++) {
                uint32_t Bf[3][4];
#pragma unroll
                for (int p = 0; p < 3; p++)
                    ldsm4(Bf[p], sb[p] + ((wn + nc * 16 + brow) * 40 + kk + bcol8) * 2);
#pragma unroll
                for (int p = 0; p < 3; p++)
#pragma unroll
                    for (int f = 0; f < 2; f++)
#pragma unroll
                        for (int j = 0; j < 2; j++)
                            mmabf(C[f][nc * 2 + j], Af[f], &Bf[p][j * 2]);
            }
        }
        __syncthreads();
    }

    long zbase = (long)blockIdx.z * BH;
#pragma unroll
    for (int f = 0; f < 2; f++) {
        int rl = m0 + wm + f * 16 + (lane >> 2);
#pragma unroll
        for (int j = 0; j < 8; j++) {
            int h = n0 + wn + j * 8 + (lane & 3) * 2;
            *(float2*)&g_part[zbase + (long)rl * H_ + h] = make_float2(C[f][j][0], C[f][j][1]);
            *(float2*)&g_part[zbase + (long)(rl + 8) * H_ + h] = make_float2(C[f][j][2], C[f][j][3]);
        }
    }
}

// --------------------------- layer-1 LIF (t=0) ------------------------------
__global__ void spike1_kernel(int t) {
    int idx = blockIdx.x * blockDim.x + threadIdx.x;
    float v = g_v1[idx], cur = g_i1[idx], s;
    lif_update(v, cur, g_inp1[(long)t * BH + idx], s);
    g_v1[idx] = v; g_i1[idx] = cur;
    g_s1h[idx] = __float2bfloat16(s);
}

// ---------------------------------------------------------------------------
// Fused per-step tail: reduce split-K partials + LIF2 -> s2 (smem),
// output GEMV + LIF-out + rate accumulate, then layer-1 LIF for step t+1.
// ---------------------------------------------------------------------------
__global__ void __launch_bounds__(512) fused_tail_kernel(
    const float* __restrict__ Wout, const float* __restrict__ b2,
    const float* __restrict__ bout, float* __restrict__ out, int t)
{
    __shared__ float s2s[H_];
    int b = blockIdx.x;
    int tid = threadIdx.x;

#pragma unroll
    for (int rep = 0; rep < 2; rep++) {
        int h = tid + rep * 512;
        int idx = b * H_ + h;
        float sum = b2[h];
#pragma unroll
        for (int z = 0; z < KSPL; z++) sum += g_part[(long)z * BH + idx];
        float v = g_v2[idx], cur = g_i2[idx], s;
        lif_update(v, cur, sum, s);
        g_v2[idx] = v; g_i2[idx] = cur;
        s2s[h] = s;
    }
    __syncthreads();

    int w = tid >> 5, lane = tid & 31;
    if (w < OUT_) {
        float sum = 0.f;
#pragma unroll 8
        for (int j = lane; j < H_; j += 32)
            sum = fmaf(s2s[j], __ldg(&Wout[w * H_ + j]), sum);
#pragma unroll
        for (int off = 16; off; off >>= 1)
            sum += __shfl_xor_sync(0xffffffff, sum, off);
        if (lane == 0) {
            int idx = b * OUT_ + w;
            float v = g_vo[idx], cur = g_io[idx], s;
            lif_update(v, cur, sum + bout[w], s);
            g_vo[idx] = v; g_io[idx] = cur;
            out[idx] += s;
        }
    }

    if (t + 1 < T_) {
#pragma unroll
        for (int rep = 0; rep < 2; rep++) {
            int h = tid + rep * 512;
            int idx = b * H_ + h;
            float v = g_v1[idx], cur = g_i1[idx], s;
            lif_update(v, cur, g_inp1[(long)(t + 1) * BH + idx], s);
            g_v1[idx] = v; g_i1[idx] = cur;
            g_s1h[idx] = __float2bfloat16(s);
        }
    }
}

// ---------------------------------------------------------------------------
extern "C" void kernel_launch(void* const* d_in, const int* in_sizes, int n_in,
                              void* d_out, int out_size)
{
    const float* x    = (const float*)d_in[0];
    const float* W1   = (const float*)d_in[1];
    const float* b1   = (const float*)d_in[2];
    const float* W2   = (const float*)d_in[3];
    const float* b2   = (const float*)d_in[4];
    const float* Wout = (const float*)d_in[5];
    const float* bout = (const float*)d_in[6];
    float* out = (float*)d_out;

    static int smem_set = 0;
    if (!smem_set) {
        cudaFuncSetAttribute(mm1_kernel, cudaFuncAttributeMaxDynamicSharedMemorySize, 61440);
        smem_set = 1;
    }

    init_kernel<<<BH / 256, 256>>>(out);

    // exact 3-limb bf16 decompositions
    conv3<<<dim3((KP + 255) / 256, B_ * T_), 256>>>(x,  g_x0,  g_x1,  g_x2,  IN_, KP);
    conv3<<<dim3((KP + 255) / 256, H_),      256>>>(W1, g_w10, g_w11, g_w12, IN_, KP);
    conv3<<<dim3((H_ + 255) / 256, H_),      256>>>(W2, g_w20, g_w21, g_w22, H_, H_);

    // Time-parallel input GEMM on tensor cores (6 limb pairs)
    mm1_kernel<<<dim3(H_ / 128, (B_ * T_) / 128), 256, 61440>>>(b1);

    spike1_kernel<<<BH / 256, 256>>>(0);

    for (int t = 0; t < T_; t++) {
        g2_kernel<<<dim3(H_ / 128, B_ / 128, KSPL), 256>>>();
        fused_tail_kernel<<<B_, 512>>>(Wout, b2, bout, out, t);
    }
}

// round 7
// speedup vs baseline: 2.2544x; 2.2544x over previous
#include <cuda_runtime.h>

// Problem dims
#define B_   256
#define T_   32
#define IN_  2312
#define H_   1024
#define OUT_ 10
#define BH   (B_ * H_)

// LIF constants
#define DT_TAUMEM 0.05f
#define DT_TAUSYN 0.2f

#define KSPL 16                     // split-K factor for GEMM2

// Device-global scratch / state
__device__ float g_inp1[(long)T_ * BH];
__device__ float g_v1[BH], g_i1[BH];
__device__ float g_v2[BH], g_i2[BH];
__device__ float g_s1[BH];
__device__ float g_part[(long)KSPL * BH];
__device__ float g_vo[B_ * OUT_], g_io[B_ * OUT_];

__device__ __forceinline__ void lif_update(float& v, float& cur, float inp, float& s) {
    float vd = v + DT_TAUMEM * (cur - v);
    float id = cur - DT_TAUSYN * cur;
    s = (vd - 1.0f) > 0.0f ? 1.0f : 0.0f;
    v = (1.0f - s) * vd;
    cur = id + inp;
}

// ---- packed f32x2 helpers (FFMA2 path) ------------------------------------
__device__ __forceinline__ unsigned long long dup2(float x) {
    unsigned long long r;
    asm("mov.b64 %0, {%1, %1};" : "=l"(r) : "f"(x));
    return r;
}
__device__ __forceinline__ unsigned long long pk2(float x, float y) {
    unsigned long long r;
    asm("mov.b64 %0, {%1, %2};" : "=l"(r) : "f"(x), "f"(y));
    return r;
}
__device__ __forceinline__ void fma2(unsigned long long& d,
                                     unsigned long long a, unsigned long long b) {
    asm("fma.rn.f32x2 %0, %1, %2, %0;" : "+l"(d) : "l"(a), "l"(b));
}
__device__ __forceinline__ float2 up2(unsigned long long v) {
    float2 f;
    asm("mov.b64 {%0, %1}, %2;" : "=f"(f.x), "=f"(f.y) : "l"(v));
    return f;
}

// ---------------------------------------------------------------------------
__global__ void init_kernel(float* __restrict__ out) {
    int idx = blockIdx.x * blockDim.x + threadIdx.x;
    if (idx < BH) {
        g_v1[idx] = 0.f; g_i1[idx] = 0.f;
        g_v2[idx] = 0.f; g_i2[idx] = 0.f;
    }
    if (idx < B_ * OUT_) {
        g_vo[idx] = 0.f; g_io[idx] = 0.f;
        out[idx] = 0.f;
    }
}

// ---------------------------------------------------------------------------
// GEMM1: g_inp1[t][b][h] = x[m=b*32+t,:] . W1[h,:] + b1[h]
// M=8192, N=1024, K=2312. Tile 128x128, BK=8, 256 thr, 8x8/thread, FFMA2.
// ---------------------------------------------------------------------------
#define G1_BM 128
#define G1_BN 128
#define G1_BK 8
#define G1_PAD 132
__global__ void __launch_bounds__(256) gemm1_kernel(
    const float* __restrict__ x, const float* __restrict__ W1,
    const float* __restrict__ b1)
{
    __shared__ float As[2][G1_BK][G1_PAD];
    __shared__ float Bs[2][G1_BK][G1_PAD];

    int tid = threadIdx.x;
    int m0 = blockIdx.y * G1_BM;
    int n0 = blockIdx.x * G1_BN;

    int lrow = tid >> 1;            // 0..127
    int lk4  = (tid & 1) * 4;       // 0 or 4
    const float* aptr = x  + (long)(m0 + lrow) * IN_ + lk4;
    const float* bptr = W1 + (long)(n0 + lrow) * IN_ + lk4;

    int tx = tid & 15;              // col group
    int ty = tid >> 4;              // row group

    unsigned long long acc[8][4];
#pragma unroll
    for (int r = 0; r < 8; r++)
#pragma unroll
        for (int c = 0; c < 4; c++) acc[r][c] = 0ULL;

    float4 ra = *(const float4*)aptr;
    float4 rb = *(const float4*)bptr;
#pragma unroll
    for (int i = 0; i < 4; i++) {
        As[0][lk4 + i][lrow] = ((const float*)&ra)[i];
        Bs[0][lk4 + i][lrow] = ((const float*)&rb)[i];
    }
    __syncthreads();

    const int nIter = IN_ / G1_BK;  // 289
    for (int it = 0; it < nIter; it++) {
        int cur = it & 1, nxt = cur ^ 1;
        if (it + 1 < nIter) {
            ra = *(const float4*)(aptr + (long)(it + 1) * G1_BK);
            rb = *(const float4*)(bptr + (long)(it + 1) * G1_BK);
        }
#pragma unroll
        for (int k = 0; k < G1_BK; k++) {
            float4 a0 = *(const float4*)&As[cur][k][ty * 4];
            float4 a1 = *(const float4*)&As[cur][k][ty * 4 + 64];
            float4 b0 = *(const float4*)&Bs[cur][k][tx * 4];
            float4 b1 = *(const float4*)&Bs[cur][k][tx * 4 + 64];
            unsigned long long ap[8], bp[4];
            ap[0] = dup2(a0.x); ap[1] = dup2(a0.y); ap[2] = dup2(a0.z); ap[3] = dup2(a0.w);
            ap[4] = dup2(a1.x); ap[5] = dup2(a1.y); ap[6] = dup2(a1.z); ap[7] = dup2(a1.w);
            bp[0] = pk2(b0.x, b0.y); bp[1] = pk2(b0.z, b0.w);
            bp[2] = pk2(b1.x, b1.y); bp[3] = pk2(b1.z, b1.w);
#pragma unroll
            for (int r = 0; r < 8; r++)
#pragma unroll
                for (int c = 0; c < 4; c++) fma2(acc[r][c], ap[r], bp[c]);
        }
        if (it + 1 < nIter) {
#pragma unroll
            for (int i = 0; i < 4; i++) {
                As[nxt][lk4 + i][lrow] = ((const float*)&ra)[i];
                Bs[nxt][lk4 + i][lrow] = ((const float*)&rb)[i];
            }
        }
        __syncthreads();
    }

#pragma unroll
    for (int r = 0; r < 8; r++) {
        int m = m0 + ty * 4 + (r & 3) + (r >> 2) * 64;
        int b = m >> 5;
        int t = m & 31;
        long orow = ((long)t * B_ + b) * H_;
#pragma unroll
        for (int c = 0; c < 4; c++) {
            int h = n0 + tx * 4 + (c & 1) * 2 + (c >> 1) * 64;
            float2 v = up2(acc[r][c]);
            g_inp1[orow + h]     = v.x + b1[h];
            g_inp1[orow + h + 1] = v.y + b1[h + 1];
        }
    }
}

// ---------------------------------------------------------------------------
// Layer-1 LIF, standalone (t=0 only)
// ---------------------------------------------------------------------------
__global__ void spike1_kernel(int t) {
    int idx = blockIdx.x * blockDim.x + threadIdx.x;
    float v = g_v1[idx], cur = g_i1[idx], s;
    lif_update(v, cur, g_inp1[(long)t * BH + idx], s);
    g_v1[idx] = v; g_i1[idx] = cur; g_s1[idx] = s;
}

// ---------------------------------------------------------------------------
// GEMM2 split-K partial with FFMA2.
// M=256, N=1024, K=1024, KSPL=16 (KC=64). Tile 64x128, BK=16, 256 thr,
// 4x8 per thread. Grid (8, 4, 16) = 512 blocks.
// ---------------------------------------------------------------------------
#define G2_BM 64
#define G2_BN 128
#define G2_BK 16
#define G2_KC (H_ / KSPL)    // 64
#define G2_PADA 68
#define G2_PADB 132
__global__ void __launch_bounds__(256) g2_partial_kernel(const float* __restrict__ W2)
{
    __shared__ float Ss[2][G2_BK][G2_PADA];
    __shared__ float Ws[2][G2_BK][G2_PADB];

    int tid = threadIdx.x;
    int m0 = blockIdx.y * G2_BM;
    int n0 = blockIdx.x * G2_BN;
    int kbase = blockIdx.z * G2_KC;

    int lrow = tid >> 2;          // 0..63
    int lk4  = (tid & 3) * 4;     // 0,4,8,12
    const float* aptr  = g_s1 + (long)(m0 + lrow) * H_ + kbase + lk4;
    const float* bptr0 = W2 + (long)(n0 + lrow) * H_ + kbase + lk4;
    const float* bptr1 = W2 + (long)(n0 + lrow + 64) * H_ + kbase + lk4;

    int tx = tid & 15;
    int ty = tid >> 4;

    unsigned long long acc[4][4];
#pragma unroll
    for (int r = 0; r < 4; r++)
#pragma unroll
        for (int c = 0; c < 4; c++) acc[r][c] = 0ULL;

    float4 ra  = *(const float4*)aptr;
    float4 rb0 = *(const float4*)bptr0;
    float4 rb1 = *(const float4*)bptr1;
#pragma unroll
    for (int i = 0; i < 4; i++) {
        Ss[0][lk4 + i][lrow] = ((const float*)&ra)[i];
        Ws[0][lk4 + i][lrow] = ((const float*)&rb0)[i];
        Ws[0][lk4 + i][lrow + 64] = ((const float*)&rb1)[i];
    }
    __syncthreads();

    const int nIter = G2_KC / G2_BK;   // 4
#pragma unroll 1
    for (int it = 0; it < nIter; it++) {
        int cur = it & 1, nxt = cur ^ 1;
        if (it + 1 < nIter) {
            ra  = *(const float4*)(aptr  + (it + 1) * G2_BK);
            rb0 = *(const float4*)(bptr0 + (it + 1) * G2_BK);
            rb1 = *(const float4*)(bptr1 + (it + 1) * G2_BK);
        }
#pragma unroll
        for (int k = 0; k < G2_BK; k++) {
            float4 a0 = *(const float4*)&Ss[cur][k][ty * 4];
            float4 b0 = *(const float4*)&Ws[cur][k][tx * 4];
            float4 b1 = *(const float4*)&Ws[cur][k][tx * 4 + 64];
            unsigned long long ap[4], bp[4];
            ap[0] = dup2(a0.x); ap[1] = dup2(a0.y); ap[2] = dup2(a0.z); ap[3] = dup2(a0.w);
            bp[0] = pk2(b0.x, b0.y); bp[1] = pk2(b0.z, b0.w);
            bp[2] = pk2(b1.x, b1.y); bp[3] = pk2(b1.z, b1.w);
#pragma unroll
            for (int r = 0; r < 4; r++)
#pragma unroll
                for (int c = 0; c < 4; c++) fma2(acc[r][c], ap[r], bp[c]);
        }
        if (it + 1 < nIter) {
#pragma unroll
            for (int i = 0; i < 4; i++) {
                Ss[nxt][lk4 + i][lrow] = ((const float*)&ra)[i];
                Ws[nxt][lk4 + i][lrow] = ((const float*)&rb0)[i];
                Ws[nxt][lk4 + i][lrow + 64] = ((const float*)&rb1)[i];
            }
        }
        __syncthreads();
    }

    long base = (long)blockIdx.z * BH;
#pragma unroll
    for (int r = 0; r < 4; r++) {
        int b = m0 + ty * 4 + r;
        long row = base + (long)b * H_;
#pragma unroll
        for (int c = 0; c < 4; c++) {
            int h = n0 + tx * 4 + (c & 1) * 2 + (c >> 1) * 64;
            float2 w = up2(acc[r][c]);
            g_part[row + h]     = w.x;
            g_part[row + h + 1] = w.y;
        }
    }
}

// ---------------------------------------------------------------------------
// Fused per-step tail: reduce split-K partials + LIF2 -> s2 (smem),
// output GEMV + LIF-out + rate accumulate, then layer-1 LIF for step t+1.
// One block per batch, 512 threads, float2-vectorized state paths.
// ---------------------------------------------------------------------------
__global__ void __launch_bounds__(512) fused_tail_kernel(
    const float* __restrict__ Wout, const float* __restrict__ b2,
    const float* __restrict__ bout, float* __restrict__ out, int t)
{
    __shared__ float s2s[H_];
    int b = blockIdx.x;
    int tid = threadIdx.x;

    {
        int h = tid * 2;                       // 512 threads x float2 = 1024
        long idx = (long)b * H_ + h;
        float2 sum = *(const float2*)&b2[h];
#pragma unroll
        for (int z = 0; z < KSPL; z++) {
            float2 p = *(const float2*)&g_part[(long)z * BH + idx];
            sum.x += p.x; sum.y += p.y;
        }
        float2 v = *(float2*)&g_v2[idx];
        float2 c = *(float2*)&g_i2[idx];
        float sx, sy;
        lif_update(v.x, c.x, sum.x, sx);
        lif_update(v.y, c.y, sum.y, sy);
        *(float2*)&g_v2[idx] = v;
        *(float2*)&g_i2[idx] = c;
        *(float2*)&s2s[h] = make_float2(sx, sy);
    }
    __syncthreads();

    int w = tid >> 5, lane = tid & 31;
    if (w < OUT_) {
        float sum = 0.f;
#pragma unroll 8
        for (int j = lane; j < H_; j += 32)
            sum = fmaf(s2s[j], __ldg(&Wout[w * H_ + j]), sum);
#pragma unroll
        for (int off = 16; off; off >>= 1)
            sum += __shfl_xor_sync(0xffffffff, sum, off);
        if (lane == 0) {
            int idx = b * OUT_ + w;
            float v = g_vo[idx], cur = g_io[idx], s;
            lif_update(v, cur, sum + bout[w], s);
            g_vo[idx] = v; g_io[idx] = cur;
            out[idx] += s;
        }
    }

    if (t + 1 < T_) {
        int h = tid * 2;
        long idx = (long)b * H_ + h;
        float2 inp = *(const float2*)&g_inp1[(long)(t + 1) * BH + idx];
        float2 v = *(float2*)&g_v1[idx];
        float2 c = *(float2*)&g_i1[idx];
        float sx, sy;
        lif_update(v.x, c.x, inp.x, sx);
        lif_update(v.y, c.y, inp.y, sy);
        *(float2*)&g_v1[idx] = v;
        *(float2*)&g_i1[idx] = c;
        *(float2*)&g_s1[idx] = make_float2(sx, sy);
    }
}

// ---------------------------------------------------------------------------
extern "C" void kernel_launch(void* const* d_in, const int* in_sizes, int n_in,
                              void* d_out, int out_size)
{
    const float* x    = (const float*)d_in[0];
    const float* W1   = (const float*)d_in[1];
    const float* b1   = (const float*)d_in[2];
    const float* W2   = (const float*)d_in[3];
    const float* b2   = (const float*)d_in[4];
    const float* Wout = (const float*)d_in[5];
    const float* bout = (const float*)d_in[6];
    float* out = (float*)d_out;

    init_kernel<<<BH / 256, 256>>>(out);

    // Time-parallel input GEMM (FFMA2)
    gemm1_kernel<<<dim3(H_ / G1_BN, (B_ * T_) / G1_BM), 256>>>(x, W1, b1);

    // First-step layer-1 LIF
    spike1_kernel<<<BH / 256, 256>>>(0);

    // Recurrence: 2 kernels per step
    for (int t = 0; t < T_; t++) {
        g2_partial_kernel<<<dim3(H_ / G2_BN, B_ / G2_BM, KSPL), 256>>>(W2);
        fused_tail_kernel<<<B_, 512>>>(Wout, b2, bout, out, t);
    }
}

// round 8
// speedup vs baseline: 2.4244x; 1.0754x over previous
#include <cuda_runtime.h>

// Problem dims
#define B_   256
#define T_   32
#define IN_  2312
#define H_   1024
#define OUT_ 10
#define BH   (B_ * H_)

// LIF constants
#define DT_TAUMEM 0.05f
#define DT_TAUSYN 0.2f

#define KSPL 8                      // split-K factor for GEMM2

// Device-global scratch / state
__device__ float g_inp1[(long)T_ * BH];
__device__ float g_v1[BH], g_i1[BH];
__device__ float g_v2[BH], g_i2[BH];
__device__ float g_s1[BH];
__device__ float g_part[(long)KSPL * BH];
__device__ float g_vo[B_ * OUT_], g_io[B_ * OUT_];

__device__ __forceinline__ void lif_update(float& v, float& cur, float inp, float& s) {
    float vd = v + DT_TAUMEM * (cur - v);
    float id = cur - DT_TAUSYN * cur;
    s = (vd - 1.0f) > 0.0f ? 1.0f : 0.0f;
    v = (1.0f - s) * vd;
    cur = id + inp;
}

// ---- packed f32x2 helpers (FFMA2 path) ------------------------------------
__device__ __forceinline__ unsigned long long dup2(float x) {
    unsigned long long r;
    asm("mov.b64 %0, {%1, %1};" : "=l"(r) : "f"(x));
    return r;
}
__device__ __forceinline__ unsigned long long pk2(float x, float y) {
    unsigned long long r;
    asm("mov.b64 %0, {%1, %2};" : "=l"(r) : "f"(x), "f"(y));
    return r;
}
__device__ __forceinline__ void fma2(unsigned long long& d,
                                     unsigned long long a, unsigned long long b) {
    asm("fma.rn.f32x2 %0, %1, %2, %0;" : "+l"(d) : "l"(a), "l"(b));
}
__device__ __forceinline__ float2 up2(unsigned long long v) {
    float2 f;
    asm("mov.b64 {%0, %1}, %2;" : "=f"(f.x), "=f"(f.y) : "l"(v));
    return f;
}

// ---------------------------------------------------------------------------
__global__ void init_kernel(float* __restrict__ out) {
    int idx = blockIdx.x * blockDim.x + threadIdx.x;
    if (idx < BH) {
        g_v1[idx] = 0.f; g_i1[idx] = 0.f;
        g_v2[idx] = 0.f; g_i2[idx] = 0.f;
    }
    if (idx < B_ * OUT_) {
        g_vo[idx] = 0.f; g_io[idx] = 0.f;
        out[idx] = 0.f;
    }
}

// ---------------------------------------------------------------------------
// GEMM1: g_inp1[t][b][h] = x[m=b*32+t,:] . W1[h,:] + b1[h]
// M=8192, N=1024, K=2312. Tile 128x128, BK=8, 256 thr, 8x8/thread, FFMA2.
// ---------------------------------------------------------------------------
#define G1_BK 8
#define G1_PAD 132
__global__ void __launch_bounds__(256) gemm1_kernel(
    const float* __restrict__ x, const float* __restrict__ W1,
    const float* __restrict__ b1)
{
    __shared__ float As[2][G1_BK][G1_PAD];
    __shared__ float Bs[2][G1_BK][G1_PAD];

    int tid = threadIdx.x;
    int m0 = blockIdx.y * 128;
    int n0 = blockIdx.x * 128;

    int lrow = tid >> 1;            // 0..127
    int lk4  = (tid & 1) * 4;       // 0 or 4
    const float* aptr = x  + (long)(m0 + lrow) * IN_ + lk4;
    const float* bptr = W1 + (long)(n0 + lrow) * IN_ + lk4;

    int tx = tid & 15;              // col group
    int ty = tid >> 4;              // row group

    unsigned long long acc[8][4];
#pragma unroll
    for (int r = 0; r < 8; r++)
#pragma unroll
        for (int c = 0; c < 4; c++) acc[r][c] = 0ULL;

    float4 ra = *(const float4*)aptr;
    float4 rb = *(const float4*)bptr;
#pragma unroll
    for (int i = 0; i < 4; i++) {
        As[0][lk4 + i][lrow] = ((const float*)&ra)[i];
        Bs[0][lk4 + i][lrow] = ((const float*)&rb)[i];
    }
    __syncthreads();

    const int nIter = IN_ / G1_BK;  // 289
    for (int it = 0; it < nIter; it++) {
        int cur = it & 1, nxt = cur ^ 1;
        if (it + 1 < nIter) {
            ra = *(const float4*)(aptr + (long)(it + 1) * G1_BK);
            rb = *(const float4*)(bptr + (long)(it + 1) * G1_BK);
        }
#pragma unroll
        for (int k = 0; k < G1_BK; k++) {
            float4 a0 = *(const float4*)&As[cur][k][ty * 4];
            float4 a1 = *(const float4*)&As[cur][k][ty * 4 + 64];
            float4 b0 = *(const float4*)&Bs[cur][k][tx * 4];
            float4 b1 = *(const float4*)&Bs[cur][k][tx * 4 + 64];
            unsigned long long ap[8], bp[4];
            ap[0] = dup2(a0.x); ap[1] = dup2(a0.y); ap[2] = dup2(a0.z); ap[3] = dup2(a0.w);
            ap[4] = dup2(a1.x); ap[5] = dup2(a1.y); ap[6] = dup2(a1.z); ap[7] = dup2(a1.w);
            bp[0] = pk2(b0.x, b0.y); bp[1] = pk2(b0.z, b0.w);
            bp[2] = pk2(b1.x, b1.y); bp[3] = pk2(b1.z, b1.w);
#pragma unroll
            for (int r = 0; r < 8; r++)
#pragma unroll
                for (int c = 0; c < 4; c++) fma2(acc[r][c], ap[r], bp[c]);
        }
        if (it + 1 < nIter) {
#pragma unroll
            for (int i = 0; i < 4; i++) {
                As[nxt][lk4 + i][lrow] = ((const float*)&ra)[i];
                Bs[nxt][lk4 + i][lrow] = ((const float*)&rb)[i];
            }
        }
        __syncthreads();
    }

#pragma unroll
    for (int r = 0; r < 8; r++) {
        int m = m0 + ty * 4 + (r & 3) + (r >> 2) * 64;
        int b = m >> 5;
        int t = m & 31;
        long orow = ((long)t * B_ + b) * H_;
#pragma unroll
        for (int c = 0; c < 4; c++) {
            int h = n0 + tx * 4 + (c & 1) * 2 + (c >> 1) * 64;
            float2 v = up2(acc[r][c]);
            g_inp1[orow + h]     = v.x + b1[h];
            g_inp1[orow + h + 1] = v.y + b1[h + 1];
        }
    }
}

// ---------------------------------------------------------------------------
// Layer-1 LIF, standalone (t=0 only)
// ---------------------------------------------------------------------------
__global__ void spike1_kernel(int t) {
    int idx = blockIdx.x * blockDim.x + threadIdx.x;
    float v = g_v1[idx], cur = g_i1[idx], s;
    lif_update(v, cur, g_inp1[(long)t * BH + idx], s);
    g_v1[idx] = v; g_i1[idx] = cur; g_s1[idx] = s;
}

// ---------------------------------------------------------------------------
// GEMM2 split-K partial: same 128x128xBK=8 FFMA2 structure as gemm1.
// g_part[z][b][h] = sum_{k in chunk z} s1[b,k]*W2[h,k]
// M=256 (2 tiles), N=1024 (8 tiles), K chunk=128 (16 iters). Grid (8,2,8)=128.
// ---------------------------------------------------------------------------
__global__ void __launch_bounds__(256) g2_partial_kernel(const float* __restrict__ W2)
{
    __shared__ float As[2][G1_BK][G1_PAD];
    __shared__ float Bs[2][G1_BK][G1_PAD];

    int tid = threadIdx.x;
    int m0 = blockIdx.y * 128;              // batch tile
    int n0 = blockIdx.x * 128;              // h tile
    int kbase = blockIdx.z * (H_ / KSPL);   // 128-wide K chunk

    int lrow = tid >> 1;
    int lk4  = (tid & 1) * 4;
    const float* aptr = g_s1 + (long)(m0 + lrow) * H_ + kbase + lk4;
    const float* bptr = W2   + (long)(n0 + lrow) * H_ + kbase + lk4;

    int tx = tid & 15;
    int ty = tid >> 4;

    unsigned long long acc[8][4];
#pragma unroll
    for (int r = 0; r < 8; r++)
#pragma unroll
        for (int c = 0; c < 4; c++) acc[r][c] = 0ULL;

    float4 ra = *(const float4*)aptr;
    float4 rb = *(const float4*)bptr;
#pragma unroll
    for (int i = 0; i < 4; i++) {
        As[0][lk4 + i][lrow] = ((const float*)&ra)[i];
        Bs[0][lk4 + i][lrow] = ((const float*)&rb)[i];
    }
    __syncthreads();

    const int nIter = (H_ / KSPL) / G1_BK;  // 16
#pragma unroll 1
    for (int it = 0; it < nIter; it++) {
        int cur = it & 1, nxt = cur ^ 1;
        if (it + 1 < nIter) {
            ra = *(const float4*)(aptr + (it + 1) * G1_BK);
            rb = *(const float4*)(bptr + (it + 1) * G1_BK);
        }
#pragma unroll
        for (int k = 0; k < G1_BK; k++) {
            float4 a0 = *(const float4*)&As[cur][k][ty * 4];
            float4 a1 = *(const float4*)&As[cur][k][ty * 4 + 64];
            float4 b0 = *(const float4*)&Bs[cur][k][tx * 4];
            float4 b1 = *(const float4*)&Bs[cur][k][tx * 4 + 64];
            unsigned long long ap[8], bp[4];
            ap[0] = dup2(a0.x); ap[1] = dup2(a0.y); ap[2] = dup2(a0.z); ap[3] = dup2(a0.w);
            ap[4] = dup2(a1.x); ap[5] = dup2(a1.y); ap[6] = dup2(a1.z); ap[7] = dup2(a1.w);
            bp[0] = pk2(b0.x, b0.y); bp[1] = pk2(b0.z, b0.w);
            bp[2] = pk2(b1.x, b1.y); bp[3] = pk2(b1.z, b1.w);
#pragma unroll
            for (int r = 0; r < 8; r++)
#pragma unroll
                for (int c = 0; c < 4; c++) fma2(acc[r][c], ap[r], bp[c]);
        }
        if (it + 1 < nIter) {
#pragma unroll
            for (int i = 0; i < 4; i++) {
                As[nxt][lk4 + i][lrow] = ((const float*)&ra)[i];
                Bs[nxt][lk4 + i][lrow] = ((const float*)&rb)[i];
            }
        }
        __syncthreads();
    }

    long zbase = (long)blockIdx.z * BH;
#pragma unroll
    for (int r = 0; r < 8; r++) {
        int b = m0 + ty * 4 + (r & 3) + (r >> 2) * 64;
        long row = zbase + (long)b * H_;
#pragma unroll
        for (int c = 0; c < 4; c++) {
            int h = n0 + tx * 4 + (c & 1) * 2 + (c >> 1) * 64;
            float2 w = up2(acc[r][c]);
            g_part[row + h]     = w.x;
            g_part[row + h + 1] = w.y;
        }
    }
}

// ---------------------------------------------------------------------------
// Fused per-step tail: reduce split-K partials + LIF2 -> s2 (smem),
// output GEMV + LIF-out + rate accumulate, then layer-1 LIF for step t+1.
// One block per batch, 512 threads, float2-vectorized state paths.
// ---------------------------------------------------------------------------
__global__ void __launch_bounds__(512) fused_tail_kernel(
    const float* __restrict__ Wout, const float* __restrict__ b2,
    const float* __restrict__ bout, float* __restrict__ out, int t)
{
    __shared__ float s2s[H_];
    int b = blockIdx.x;
    int tid = threadIdx.x;

    {
        int h = tid * 2;                       // 512 threads x float2 = 1024
        long idx = (long)b * H_ + h;
        float2 sum = *(const float2*)&b2[h];
#pragma unroll
        for (int z = 0; z < KSPL; z++) {
            float2 p = *(const float2*)&g_part[(long)z * BH + idx];
            sum.x += p.x; sum.y += p.y;
        }
        float2 v = *(float2*)&g_v2[idx];
        float2 c = *(float2*)&g_i2[idx];
        float sx, sy;
        lif_update(v.x, c.x, sum.x, sx);
        lif_update(v.y, c.y, sum.y, sy);
        *(float2*)&g_v2[idx] = v;
        *(float2*)&g_i2[idx] = c;
        *(float2*)&s2s[h] = make_float2(sx, sy);
    }
    __syncthreads();

    int w = tid >> 5, lane = tid & 31;
    if (w < OUT_) {
        float sum = 0.f;
#pragma unroll 8
        for (int j = lane; j < H_; j += 32)
            sum = fmaf(s2s[j], __ldg(&Wout[w * H_ + j]), sum);
#pragma unroll
        for (int off = 16; off; off >>= 1)
            sum += __shfl_xor_sync(0xffffffff, sum, off);
        if (lane == 0) {
            int idx = b * OUT_ + w;
            float v = g_vo[idx], cur = g_io[idx], s;
            lif_update(v, cur, sum + bout[w], s);
            g_vo[idx] = v; g_io[idx] = cur;
            out[idx] += s;
        }
    }

    if (t + 1 < T_) {
        int h = tid * 2;
        long idx = (long)b * H_ + h;
        float2 inp = *(const float2*)&g_inp1[(long)(t + 1) * BH + idx];
        float2 v = *(float2*)&g_v1[idx];
        float2 c = *(float2*)&g_i1[idx];
        float sx, sy;
        lif_update(v.x, c.x, inp.x, sx);
        lif_update(v.y, c.y, inp.y, sy);
        *(float2*)&g_v1[idx] = v;
        *(float2*)&g_i1[idx] = c;
        *(float2*)&g_s1[idx] = make_float2(sx, sy);
    }
}

// ---------------------------------------------------------------------------
extern "C" void kernel_launch(void* const* d_in, const int* in_sizes, int n_in,
                              void* d_out, int out_size)
{
    const float* x    = (const float*)d_in[0];
    const float* W1   = (const float*)d_in[1];
    const float* b1   = (const float*)d_in[2];
    const float* W2   = (const float*)d_in[3];
    const float* b2   = (const float*)d_in[4];
    const float* Wout = (const float*)d_in[5];
    const float* bout = (const float*)d_in[6];
    float* out = (float*)d_out;

    init_kernel<<<BH / 256, 256>>>(out);

    // Time-parallel input GEMM (FFMA2)
    gemm1_kernel<<<dim3(H_ / 128, (B_ * T_) / 128), 256>>>(x, W1, b1);

    // First-step layer-1 LIF
    spike1_kernel<<<BH / 256, 256>>>(0);

    // Recurrence: 2 kernels per step
    for (int t = 0; t < T_; t++) {
        g2_partial_kernel<<<dim3(H_ / 128, B_ / 128, KSPL), 256>>>(W2);
        fused_tail_kernel<<<B_, 512>>>(Wout, b2, bout, out, t);
    }
}